// round 1
// baseline (speedup 1.0000x reference)
#include <cuda_runtime.h>
#include <cuda_fp16.h>
#include <mma.h>

using namespace nvcuda;

// Problem constants
#define B_    4
#define N_    2048
#define KC_   2048
#define D_    1024
#define H_    16
#define HD_   64
#define MROWS 8192            // B*N == B*KC
#define OUT_ELEMS (MROWS * D_) // 8388608

// -------------------- device scratch (static; no allocation) --------------------
__device__ __half g_xh   [MROWS * D_];      // x in fp16
__device__ __half g_ctxnh[MROWS * D_];      // rmsnorm(ctx) in fp16
__device__ __half g_qwh  [D_ * D_];
__device__ __half g_kvwh [D_ * 2 * D_];
__device__ __half g_pwh  [D_ * D_];
__device__ float  g_qf   [MROWS * D_];      // q fp32 (pre-bias)
__device__ __half g_qh   [MROWS * D_];      // q fp16
__device__ float  g_kvf  [MROWS * 2 * D_];  // kv fp32 (pre-bias)
__device__ __half g_kvh  [MROWS * 2 * D_];  // kv fp16
__device__ __half g_oh   [MROWS * D_];      // attention output fp16

// -------------------- elementwise helpers --------------------
__global__ void f2h_kernel(const float4* __restrict__ src, __half2* __restrict__ dst, int n4) {
    int i = blockIdx.x * 256 + threadIdx.x;
    if (i < n4) {
        float4 v = src[i];
        dst[2 * i]     = __floats2half2_rn(v.x, v.y);
        dst[2 * i + 1] = __floats2half2_rn(v.z, v.w);
    }
}

// dst[i] = half(src[i] + bias[i & (N-1)])   (N power of two)
__global__ void bias_f2h_kernel(const float* __restrict__ src, const float* __restrict__ bias,
                                __half* __restrict__ dst, int nmask, int total) {
    int i = blockIdx.x * 256 + threadIdx.x;
    if (i < total) dst[i] = __float2half(src[i] + bias[i & nmask]);
}

// out[i] += bias[i & (N-1)]
__global__ void bias_add_kernel(float* __restrict__ out, const float* __restrict__ bias,
                                int nmask, int total) {
    int i = blockIdx.x * 256 + threadIdx.x;
    if (i < total) out[i] += bias[i & nmask];
}

__global__ void tail_fill_kernel(float* __restrict__ out, int start, int end, float val) {
    int i = start + blockIdx.x * 256 + threadIdx.x;
    if (i < end) out[i] = val;
}

// -------------------- rmsnorm(ctx) -> fp16 --------------------
// one block (256 threads) per row of 1024 floats
__global__ void rmsnorm_kernel(const float* __restrict__ ctx) {
    __shared__ float red[8];
    int row = blockIdx.x;
    int tid = threadIdx.x;
    float4 v = reinterpret_cast<const float4*>(ctx + (size_t)row * D_)[tid];
    float s = v.x * v.x + v.y * v.y + v.z * v.z + v.w * v.w;
    #pragma unroll
    for (int o = 16; o; o >>= 1) s += __shfl_xor_sync(0xffffffffu, s, o);
    if ((tid & 31) == 0) red[tid >> 5] = s;
    __syncthreads();
    if (tid < 8) {
        float t = red[tid];
        #pragma unroll
        for (int o = 4; o; o >>= 1) t += __shfl_xor_sync(0xffu, t, o);
        if (tid == 0) red[0] = t;
    }
    __syncthreads();
    float inv = rsqrtf(red[0] * (1.0f / 1024.0f) + 1e-6f);
    __half2* d = reinterpret_cast<__half2*>(g_ctxnh + (size_t)row * D_);
    d[2 * tid]     = __floats2half2_rn(v.x * inv, v.y * inv);
    d[2 * tid + 1] = __floats2half2_rn(v.z * inv, v.w * inv);
}

// -------------------- generic fp16 wmma GEMM: C(f32) = A(f16) * B(f16) --------------------
// block tile 128x128, 256 threads = 8 warps (4x2), warp tile 32x64, K-chunk 32
__device__ __forceinline__ void gemm_body(const __half* __restrict__ A,
                                          const __half* __restrict__ Bm,
                                          float* __restrict__ C, int N, int K) {
    __shared__ __align__(16) __half As[128][40];   // 80 B/row (16B multiple)
    __shared__ __align__(16) __half Bs[32][136];   // 272 B/row
    int bm = blockIdx.y * 128;
    int bn = blockIdx.x * 128;
    int tid = threadIdx.x;
    int warp = tid >> 5;
    int wm = warp >> 1, wn = warp & 1;

    wmma::fragment<wmma::accumulator, 16, 16, 16, float> acc[2][4];
    #pragma unroll
    for (int m = 0; m < 2; m++)
        #pragma unroll
        for (int n = 0; n < 4; n++) wmma::fill_fragment(acc[m][n], 0.0f);

    for (int k0 = 0; k0 < K; k0 += 32) {
        __syncthreads();
        // A tile: 128x32 halves = 512 uint4
        for (int i = tid; i < 512; i += 256) {
            int r = i >> 2, c = (i & 3) * 8;
            *reinterpret_cast<uint4*>(&As[r][c]) =
                *reinterpret_cast<const uint4*>(&A[(size_t)(bm + r) * K + k0 + c]);
        }
        // B tile: 32x128 halves = 512 uint4
        for (int i = tid; i < 512; i += 256) {
            int r = i >> 4, c = (i & 15) * 8;
            *reinterpret_cast<uint4*>(&Bs[r][c]) =
                *reinterpret_cast<const uint4*>(&Bm[(size_t)(k0 + r) * N + bn + c]);
        }
        __syncthreads();
        #pragma unroll
        for (int kk = 0; kk < 2; kk++) {
            wmma::fragment<wmma::matrix_a, 16, 16, 16, __half, wmma::row_major> af[2];
            wmma::fragment<wmma::matrix_b, 16, 16, 16, __half, wmma::row_major> bf[4];
            #pragma unroll
            for (int m = 0; m < 2; m++)
                wmma::load_matrix_sync(af[m], &As[wm * 32 + m * 16][kk * 16], 40);
            #pragma unroll
            for (int n = 0; n < 4; n++)
                wmma::load_matrix_sync(bf[n], &Bs[kk * 16][wn * 64 + n * 16], 136);
            #pragma unroll
            for (int m = 0; m < 2; m++)
                #pragma unroll
                for (int n = 0; n < 4; n++)
                    wmma::mma_sync(acc[m][n], af[m], bf[n], acc[m][n]);
        }
    }
    #pragma unroll
    for (int m = 0; m < 2; m++)
        #pragma unroll
        for (int n = 0; n < 4; n++)
            wmma::store_matrix_sync(&C[(size_t)(bm + wm * 32 + m * 16) * N + bn + wn * 64 + n * 16],
                                    acc[m][n], N, wmma::mem_row_major);
}

__global__ void gemm_q_kernel()            { gemm_body(g_xh,    g_qwh,  g_qf,  1024, 1024); }
__global__ void gemm_kv_kernel()           { gemm_body(g_ctxnh, g_kvwh, g_kvf, 2048, 1024); }
__global__ void gemm_proj_kernel(float* o) { gemm_body(g_oh,    g_pwh,  o,     1024, 1024); }

// -------------------- flash attention, fixed-offset softmax --------------------
// grid (N/64, H, B), 256 threads = 8 warps (4 row-blocks x 2 col-blocks)
// Since logits are clipped to [-10,10], exp(logit) is in [4.5e-5, 2.2e4]:
// no running max needed -> O accumulates in fragments, single divide at end.
__global__ void flash_kernel() {
    __shared__ __align__(16) __half Qs[64][72];
    __shared__ __align__(16) __half Ks[64][72];
    __shared__ __align__(16) __half Vs[64][72];
    __shared__ __align__(16) float  Ss[64][68];   // aliased as P (halves, ld=136) after exp
    __shared__ float lsum[64];

    int b = blockIdx.z, h = blockIdx.y, n0 = blockIdx.x * 64;
    int tid = threadIdx.x;
    int warp = tid >> 5;
    int rw = warp >> 1;    // 0..3 : 16-row block
    int cw = warp & 1;     // 0..1 : 32-col block

    // load Q tile (64x64 halves = 512 uint4)
    for (int i = tid; i < 512; i += 256) {
        int r = i >> 3, c = (i & 7) * 8;
        *reinterpret_cast<uint4*>(&Qs[r][c]) =
            *reinterpret_cast<const uint4*>(&g_qh[((size_t)(b * N_ + n0 + r)) * D_ + h * HD_ + c]);
    }
    if (tid < 64) lsum[tid] = 0.0f;

    wmma::fragment<wmma::accumulator, 16, 16, 16, float> oacc[2];
    wmma::fill_fragment(oacc[0], 0.0f);
    wmma::fill_fragment(oacc[1], 0.0f);

    for (int kc0 = 0; kc0 < KC_; kc0 += 64) {
        __syncthreads();  // protect Ks/Vs/Ss from prior iteration readers
        for (int i = tid; i < 512; i += 256) {
            int r = i >> 3, c = (i & 7) * 8;
            size_t base = (size_t)(b * KC_ + kc0 + r) * (2 * D_);
            *reinterpret_cast<uint4*>(&Ks[r][c]) =
                *reinterpret_cast<const uint4*>(&g_kvh[base + h * HD_ + c]);
            *reinterpret_cast<uint4*>(&Vs[r][c]) =
                *reinterpret_cast<const uint4*>(&g_kvh[base + D_ + h * HD_ + c]);
        }
        __syncthreads();

        // S = Q * K^T   (warp: rows [16rw,+16), key-cols [32cw,+32))
        wmma::fragment<wmma::accumulator, 16, 16, 16, float> sfrag[2];
        wmma::fill_fragment(sfrag[0], 0.0f);
        wmma::fill_fragment(sfrag[1], 0.0f);
        #pragma unroll
        for (int kf = 0; kf < 4; kf++) {
            wmma::fragment<wmma::matrix_a, 16, 16, 16, __half, wmma::row_major> af;
            wmma::load_matrix_sync(af, &Qs[rw * 16][kf * 16], 72);
            #pragma unroll
            for (int nf = 0; nf < 2; nf++) {
                wmma::fragment<wmma::matrix_b, 16, 16, 16, __half, wmma::col_major> bf;
                wmma::load_matrix_sync(bf, &Ks[cw * 32 + nf * 16][kf * 16], 72);
                wmma::mma_sync(sfrag[nf], af, bf, sfrag[nf]);
            }
        }
        #pragma unroll
        for (int nf = 0; nf < 2; nf++)
            wmma::store_matrix_sync(&Ss[rw * 16][cw * 32 + nf * 16], sfrag[nf], 68,
                                    wmma::mem_row_major);
        __syncthreads();

        // P = exp(clip(S*SCALE)) written in place as fp16; accumulate row sums.
        // row r is owned entirely by warp r/8, so __syncwarp orders read->write.
        {
            int row = tid >> 2, cseg = (tid & 3) * 16;
            float v[16];
            #pragma unroll
            for (int j = 0; j < 16; j++) v[j] = Ss[row][cseg + j];
            __syncwarp();
            float s = 0.0f;
            __half2* prow = reinterpret_cast<__half2*>(&Ss[row][0]);
            #pragma unroll
            for (int j = 0; j < 8; j++) {
                float a = fminf(fmaxf(v[2 * j] * 0.125f, -10.0f), 10.0f);
                float c = fminf(fmaxf(v[2 * j + 1] * 0.125f, -10.0f), 10.0f);
                a = __expf(a);
                c = __expf(c);
                s += a + c;
                prow[(cseg >> 1) + j] = __floats2half2_rn(a, c);
            }
            s += __shfl_xor_sync(0xffffffffu, s, 1);
            s += __shfl_xor_sync(0xffffffffu, s, 2);
            if ((tid & 3) == 0) lsum[row] += s;
        }
        __syncthreads();

        // O += P * V   (warp: rows [16rw,+16), d-cols [32cw,+32))
        const __half* Pbase = reinterpret_cast<const __half*>(&Ss[0][0]);
        #pragma unroll
        for (int kf = 0; kf < 4; kf++) {
            wmma::fragment<wmma::matrix_a, 16, 16, 16, __half, wmma::row_major> af;
            wmma::load_matrix_sync(af, Pbase + (size_t)(rw * 16) * 136 + kf * 16, 136);
            #pragma unroll
            for (int nf = 0; nf < 2; nf++) {
                wmma::fragment<wmma::matrix_b, 16, 16, 16, __half, wmma::row_major> bf;
                wmma::load_matrix_sync(bf, &Vs[kf * 16][cw * 32 + nf * 16], 72);
                wmma::mma_sync(oacc[nf], af, bf, oacc[nf]);
            }
        }
    }
    __syncthreads();
    #pragma unroll
    for (int nf = 0; nf < 2; nf++)
        wmma::store_matrix_sync(&Ss[rw * 16][cw * 32 + nf * 16], oacc[nf], 68,
                                wmma::mem_row_major);
    __syncthreads();
    {
        int row = tid >> 2, cseg = (tid & 3) * 16;
        float inv = 1.0f / lsum[row];
        size_t base = (size_t)(b * N_ + n0 + row) * D_ + h * HD_ + cseg;
        #pragma unroll
        for (int j = 0; j < 16; j++)
            g_oh[base + j] = __float2half(Ss[row][cseg + j] * inv);
    }
}

// -------------------- host launch --------------------
extern "C" void kernel_launch(void* const* d_in, const int* in_sizes, int n_in,
                              void* d_out, int out_size) {
    const float* x      = (const float*)d_in[0];
    const float* ctx    = (const float*)d_in[1];
    const float* q_w    = (const float*)d_in[2];
    const float* q_b    = (const float*)d_in[3];
    const float* kv_w   = (const float*)d_in[4];
    const float* kv_b   = (const float*)d_in[5];
    const float* proj_w = (const float*)d_in[6];
    const float* proj_b = (const float*)d_in[7];
    float* out = (float*)d_out;

    __half *p_xh, *p_qwh, *p_kvwh, *p_pwh, *p_qh, *p_kvh;
    float  *p_qf, *p_kvf;
    cudaGetSymbolAddress((void**)&p_xh,   g_xh);
    cudaGetSymbolAddress((void**)&p_qwh,  g_qwh);
    cudaGetSymbolAddress((void**)&p_kvwh, g_kvwh);
    cudaGetSymbolAddress((void**)&p_pwh,  g_pwh);
    cudaGetSymbolAddress((void**)&p_qf,   g_qf);
    cudaGetSymbolAddress((void**)&p_qh,   g_qh);
    cudaGetSymbolAddress((void**)&p_kvf,  g_kvf);
    cudaGetSymbolAddress((void**)&p_kvh,  g_kvh);

    // fp32 -> fp16 conversions
    {
        int n4 = (MROWS * D_) / 4;
        f2h_kernel<<<(n4 + 255) / 256, 256>>>((const float4*)x, (__half2*)p_xh, n4);
    }
    {
        int n4 = (D_ * D_) / 4;
        f2h_kernel<<<(n4 + 255) / 256, 256>>>((const float4*)q_w, (__half2*)p_qwh, n4);
        f2h_kernel<<<(n4 + 255) / 256, 256>>>((const float4*)proj_w, (__half2*)p_pwh, n4);
    }
    {
        int n4 = (D_ * 2 * D_) / 4;
        f2h_kernel<<<(n4 + 255) / 256, 256>>>((const float4*)kv_w, (__half2*)p_kvwh, n4);
    }
    // rmsnorm(ctx) -> fp16
    rmsnorm_kernel<<<MROWS, 256>>>(ctx);

    // q = x @ q_w + q_b
    gemm_q_kernel<<<dim3(1024 / 128, MROWS / 128), 256>>>();
    bias_f2h_kernel<<<(MROWS * D_ + 255) / 256, 256>>>(p_qf, q_b, p_qh, D_ - 1, MROWS * D_);

    // kv = ctxn @ kv_w + kv_b
    gemm_kv_kernel<<<dim3(2048 / 128, MROWS / 128), 256>>>();
    bias_f2h_kernel<<<(MROWS * 2 * D_ + 255) / 256, 256>>>(p_kvf, kv_b, p_kvh, 2 * D_ - 1,
                                                           MROWS * 2 * D_);

    // attention
    flash_kernel<<<dim3(N_ / 64, H_, B_), 256>>>();

    // out = attn_out @ proj_w + proj_b
    gemm_proj_kernel<<<dim3(1024 / 128, MROWS / 128), 256>>>(out);
    bias_add_kernel<<<(MROWS * D_ + 255) / 256, 256>>>(out, proj_b, D_ - 1, MROWS * D_);

    // attn.mean() == 1/K exactly (softmax rows sum to 1)
    if (out_size > OUT_ELEMS) {
        int tail = out_size - OUT_ELEMS;
        tail_fill_kernel<<<(tail + 255) / 256, 256>>>(out, OUT_ELEMS, out_size,
                                                      1.0f / (float)KC_);
    }
}

// round 7
// speedup vs baseline: 1.5132x; 1.5132x over previous
#include <cuda_runtime.h>
#include <cuda_fp16.h>
#include <cuda_pipeline.h>
#include <mma.h>

using namespace nvcuda;

#define B_    4
#define N_    2048
#define KC_   2048
#define D_    1024
#define H_    16
#define HD_   64
#define MROWS 8192
#define OUT_ELEMS (MROWS * D_)

// -------------------- device scratch (static; no allocation) --------------------
__device__ __half g_xh   [MROWS * D_];
__device__ __half g_ctxnh[MROWS * D_];
__device__ __half g_qwh  [D_ * D_];
__device__ __half g_kvwh [D_ * 2 * D_];
__device__ __half g_pwh  [D_ * D_];
__device__ __half g_qh   [MROWS * D_];
__device__ __half g_kvh  [MROWS * 2 * D_];
__device__ __half g_oh   [MROWS * D_];

// -------------------- elementwise --------------------
__global__ void f2h_kernel(const float4* __restrict__ src, __half2* __restrict__ dst, int n4) {
    int i = blockIdx.x * 256 + threadIdx.x;
    if (i < n4) {
        float4 v = src[i];
        dst[2 * i]     = __floats2half2_rn(v.x, v.y);
        dst[2 * i + 1] = __floats2half2_rn(v.z, v.w);
    }
}

__global__ void tail_fill_kernel(float* __restrict__ out, int start, int end, float val) {
    int i = start + blockIdx.x * 256 + threadIdx.x;
    if (i < end) out[i] = val;
}

// -------------------- rmsnorm(ctx) -> fp16 --------------------
__global__ void rmsnorm_kernel(const float* __restrict__ ctx) {
    __shared__ float red[8];
    int row = blockIdx.x;
    int tid = threadIdx.x;
    float4 v = reinterpret_cast<const float4*>(ctx + (size_t)row * D_)[tid];
    float s = v.x * v.x + v.y * v.y + v.z * v.z + v.w * v.w;
    #pragma unroll
    for (int o = 16; o; o >>= 1) s += __shfl_xor_sync(0xffffffffu, s, o);
    if ((tid & 31) == 0) red[tid >> 5] = s;
    __syncthreads();
    if (tid < 8) {
        float t = red[tid];
        #pragma unroll
        for (int o = 4; o; o >>= 1) t += __shfl_xor_sync(0xffu, t, o);
        if (tid == 0) red[0] = t;
    }
    __syncthreads();
    float inv = rsqrtf(red[0] * (1.0f / 1024.0f) + 1e-6f);
    __half2* d = reinterpret_cast<__half2*>(g_ctxnh + (size_t)row * D_);
    d[2 * tid]     = __floats2half2_rn(v.x * inv, v.y * inv);
    d[2 * tid + 1] = __floats2half2_rn(v.z * inv, v.w * inv);
}

// -------------------- pipelined wmma GEMM with fused bias epilogue --------------------
// block tile 128x128, 256 threads = 8 warps (4x2), warp tile 32x64, K-chunk 32,
// 2-stage double buffer via __pipeline_memcpy_async. half_out: 1 -> fp16 to Ch,
// 0 -> fp32 to Cf. Bias is added in the epilogue in both cases.
__device__ __forceinline__ void gemm_core(const __half* __restrict__ A,
                                          const __half* __restrict__ Bm,
                                          const float* __restrict__ bias,
                                          float* __restrict__ Cf,
                                          __half* __restrict__ Ch,
                                          int N, int K, int half_out) {
    __shared__ __align__(16) __half As[2][128][40];
    __shared__ __align__(16) __half Bs[2][32][136];
    const int bm = blockIdx.y * 128;
    const int bn = blockIdx.x * 128;
    const int tid = threadIdx.x;
    const int warp = tid >> 5;
    const int lane = tid & 31;
    const int wm = warp >> 1;
    const int wn = warp & 1;

    wmma::fragment<wmma::accumulator, 16, 16, 16, float> acc[2][4];
    #pragma unroll
    for (int m = 0; m < 2; m++) {
        #pragma unroll
        for (int n = 0; n < 4; n++) {
            wmma::fill_fragment(acc[m][n], 0.0f);
        }
    }

    const int NC = K >> 5;

    // prologue: prefetch chunk 0 into stage 0
    #pragma unroll
    for (int rep = 0; rep < 2; rep++) {
        int i = tid + rep * 256;
        int r = i >> 2;
        int c = (i & 3) * 8;
        __pipeline_memcpy_async(&As[0][r][c], &A[(size_t)(bm + r) * K + c], 16);
        int rb = i >> 4;
        int cb = (i & 15) * 8;
        __pipeline_memcpy_async(&Bs[0][rb][cb], &Bm[(size_t)rb * N + bn + cb], 16);
    }
    __pipeline_commit();

    for (int cix = 0; cix < NC; cix++) {
        if (cix + 1 < NC) {
            int s = (cix + 1) & 1;
            int k0 = (cix + 1) << 5;
            #pragma unroll
            for (int rep = 0; rep < 2; rep++) {
                int i = tid + rep * 256;
                int r = i >> 2;
                int c = (i & 3) * 8;
                __pipeline_memcpy_async(&As[s][r][c], &A[(size_t)(bm + r) * K + k0 + c], 16);
                int rb = i >> 4;
                int cb = (i & 15) * 8;
                __pipeline_memcpy_async(&Bs[s][rb][cb], &Bm[(size_t)(k0 + rb) * N + bn + cb], 16);
            }
            __pipeline_commit();
            __pipeline_wait_prior(1);
        } else {
            __pipeline_wait_prior(0);
        }
        __syncthreads();
        int s = cix & 1;
        #pragma unroll
        for (int kk = 0; kk < 2; kk++) {
            wmma::fragment<wmma::matrix_a, 16, 16, 16, __half, wmma::row_major> af[2];
            wmma::fragment<wmma::matrix_b, 16, 16, 16, __half, wmma::row_major> bf[4];
            #pragma unroll
            for (int m = 0; m < 2; m++) {
                wmma::load_matrix_sync(af[m], &As[s][wm * 32 + m * 16][kk * 16], 40);
            }
            #pragma unroll
            for (int n = 0; n < 4; n++) {
                wmma::load_matrix_sync(bf[n], &Bs[s][kk * 16][wn * 64 + n * 16], 136);
            }
            #pragma unroll
            for (int m = 0; m < 2; m++) {
                #pragma unroll
                for (int n = 0; n < 4; n++) {
                    wmma::mma_sync(acc[m][n], af[m], bf[n], acc[m][n]);
                }
            }
        }
        __syncthreads();
    }

    // fused bias (+convert) epilogue through a per-warp 16x20 float staging tile
    float* stg = reinterpret_cast<float*>(&As[0][0][0]) + warp * 320;
    #pragma unroll
    for (int m = 0; m < 2; m++) {
        #pragma unroll
        for (int n = 0; n < 4; n++) {
            wmma::store_matrix_sync(stg, acc[m][n], 20, wmma::mem_row_major);
            __syncwarp();
            int row = lane >> 1;
            int c0 = (lane & 1) * 8;
            int gr = bm + wm * 32 + m * 16 + row;
            int gc = bn + wn * 64 + n * 16 + c0;
            float4 b0 = *reinterpret_cast<const float4*>(&bias[gc]);
            float4 b1 = *reinterpret_cast<const float4*>(&bias[gc + 4]);
            const float* sp = stg + row * 20 + c0;
            if (half_out) {
                __half2 hv[4];
                hv[0] = __floats2half2_rn(sp[0] + b0.x, sp[1] + b0.y);
                hv[1] = __floats2half2_rn(sp[2] + b0.z, sp[3] + b0.w);
                hv[2] = __floats2half2_rn(sp[4] + b1.x, sp[5] + b1.y);
                hv[3] = __floats2half2_rn(sp[6] + b1.z, sp[7] + b1.w);
                *reinterpret_cast<uint4*>(&Ch[(size_t)gr * N + gc]) =
                    *reinterpret_cast<uint4*>(hv);
            } else {
                float4 o0 = make_float4(sp[0] + b0.x, sp[1] + b0.y, sp[2] + b0.z, sp[3] + b0.w);
                float4 o1 = make_float4(sp[4] + b1.x, sp[5] + b1.y, sp[6] + b1.z, sp[7] + b1.w);
                *reinterpret_cast<float4*>(&Cf[(size_t)gr * N + gc]) = o0;
                *reinterpret_cast<float4*>(&Cf[(size_t)gr * N + gc + 4]) = o1;
            }
            __syncwarp();
        }
    }
}

__global__ void __launch_bounds__(256) gemm_q_kernel(const float* qb) {
    gemm_core(g_xh, g_qwh, qb, 0, g_qh, 1024, 1024, 1);
}
__global__ void __launch_bounds__(256) gemm_kv_kernel(const float* kvb) {
    gemm_core(g_ctxnh, g_kvwh, kvb, 0, g_kvh, 2048, 1024, 1);
}
__global__ void __launch_bounds__(256) gemm_proj_kernel(const float* pb, float* out) {
    gemm_core(g_oh, g_pwh, pb, out, 0, 1024, 1024, 0);
}

// -------------------- flash attention (wmma, pipelined K/V, fixed-offset softmax) ----
// grid (N/64, H, B), 256 threads = 8 warps (4 row-blocks x 2 col-blocks).
// Logits clipped to [-10,10] -> exp in [4.5e-5, 2.2e4]: no running max needed,
// O stays in wmma accumulator fragments across the whole KV loop; single divide at end.
// K/V tiles are double-buffered with __pipeline_memcpy_async.
__global__ void __launch_bounds__(256) flash_kernel() {
    __shared__ __align__(16) __half Qs[64][72];
    __shared__ __align__(16) __half Ks[2][64][72];
    __shared__ __align__(16) __half Vs[2][64][72];
    __shared__ __align__(16) float  Ss[64][68];   // aliased as P (halves, ld=136) after exp
    __shared__ float lsum[64];

    const int b = blockIdx.z;
    const int h = blockIdx.y;
    const int n0 = blockIdx.x * 64;
    const int tid = threadIdx.x;
    const int warp = tid >> 5;
    const int rw = warp >> 1;    // 0..3 : 16-row block
    const int cw = warp & 1;     // 0..1 : 32-col block

    // load Q tile (64x64 halves = 512 uint4) with plain vector loads
    for (int i = tid; i < 512; i += 256) {
        int r = i >> 3;
        int c = (i & 7) * 8;
        *reinterpret_cast<uint4*>(&Qs[r][c]) =
            *reinterpret_cast<const uint4*>(&g_qh[((size_t)(b * N_ + n0 + r)) * D_ + h * HD_ + c]);
    }
    if (tid < 64) lsum[tid] = 0.0f;

    // prefetch K/V chunk 0 into stage 0 (each tile 64 rows x 64 halves = 8 x 16B per row)
    #pragma unroll
    for (int rep = 0; rep < 2; rep++) {
        int i = tid + rep * 256;
        int r = i >> 3;
        int sg = i & 7;
        size_t base = (size_t)(b * KC_ + r) * (2 * D_) + h * HD_ + sg * 8;
        __pipeline_memcpy_async(&Ks[0][r][sg * 8], &g_kvh[base], 16);
        __pipeline_memcpy_async(&Vs[0][r][sg * 8], &g_kvh[base + D_], 16);
    }
    __pipeline_commit();

    wmma::fragment<wmma::accumulator, 16, 16, 16, float> oacc[2];
    wmma::fill_fragment(oacc[0], 0.0f);
    wmma::fill_fragment(oacc[1], 0.0f);

    const int NC = KC_ / 64;   // 32
    for (int kc = 0; kc < NC; kc++) {
        __syncthreads();   // prior iteration's readers done before refilling their stage
        if (kc + 1 < NC) {
            int s = (kc + 1) & 1;
            int kc0 = (kc + 1) * 64;
            #pragma unroll
            for (int rep = 0; rep < 2; rep++) {
                int i = tid + rep * 256;
                int r = i >> 3;
                int sg = i & 7;
                size_t base = (size_t)(b * KC_ + kc0 + r) * (2 * D_) + h * HD_ + sg * 8;
                __pipeline_memcpy_async(&Ks[s][r][sg * 8], &g_kvh[base], 16);
                __pipeline_memcpy_async(&Vs[s][r][sg * 8], &g_kvh[base + D_], 16);
            }
            __pipeline_commit();
            __pipeline_wait_prior(1);
        } else {
            __pipeline_wait_prior(0);
        }
        __syncthreads();
        int s = kc & 1;

        // S = Q * K^T   (warp: rows [16rw,+16), key-cols [32cw,+32))
        wmma::fragment<wmma::accumulator, 16, 16, 16, float> sfrag[2];
        wmma::fill_fragment(sfrag[0], 0.0f);
        wmma::fill_fragment(sfrag[1], 0.0f);
        #pragma unroll
        for (int kf = 0; kf < 4; kf++) {
            wmma::fragment<wmma::matrix_a, 16, 16, 16, __half, wmma::row_major> af;
            wmma::load_matrix_sync(af, &Qs[rw * 16][kf * 16], 72);
            #pragma unroll
            for (int nf = 0; nf < 2; nf++) {
                wmma::fragment<wmma::matrix_b, 16, 16, 16, __half, wmma::col_major> bf;
                wmma::load_matrix_sync(bf, &Ks[s][cw * 32 + nf * 16][kf * 16], 72);
                wmma::mma_sync(sfrag[nf], af, bf, sfrag[nf]);
            }
        }
        #pragma unroll
        for (int nf = 0; nf < 2; nf++) {
            wmma::store_matrix_sync(&Ss[rw * 16][cw * 32 + nf * 16], sfrag[nf], 68,
                                    wmma::mem_row_major);
        }
        __syncthreads();

        // P = exp(clip(S*SCALE)) written in place as fp16; accumulate row sums.
        {
            int row = tid >> 2;
            int cseg = (tid & 3) * 16;
            float v[16];
            #pragma unroll
            for (int j = 0; j < 16; j++) v[j] = Ss[row][cseg + j];
            __syncwarp();
            float sacc = 0.0f;
            __half2* prow = reinterpret_cast<__half2*>(&Ss[row][0]);
            #pragma unroll
            for (int j = 0; j < 8; j++) {
                float a = fminf(fmaxf(v[2 * j] * 0.125f, -10.0f), 10.0f);
                float c2 = fminf(fmaxf(v[2 * j + 1] * 0.125f, -10.0f), 10.0f);
                a = __expf(a);
                c2 = __expf(c2);
                sacc += a + c2;
                prow[(cseg >> 1) + j] = __floats2half2_rn(a, c2);
            }
            sacc += __shfl_xor_sync(0xffffffffu, sacc, 1);
            sacc += __shfl_xor_sync(0xffffffffu, sacc, 2);
            if ((tid & 3) == 0) lsum[row] += sacc;
        }
        __syncthreads();

        // O += P * V   (warp: rows [16rw,+16), d-cols [32cw,+32))
        const __half* Pbase = reinterpret_cast<const __half*>(&Ss[0][0]);
        #pragma unroll
        for (int kf = 0; kf < 4; kf++) {
            wmma::fragment<wmma::matrix_a, 16, 16, 16, __half, wmma::row_major> af;
            wmma::load_matrix_sync(af, Pbase + (size_t)(rw * 16) * 136 + kf * 16, 136);
            #pragma unroll
            for (int nf = 0; nf < 2; nf++) {
                wmma::fragment<wmma::matrix_b, 16, 16, 16, __half, wmma::row_major> bf;
                wmma::load_matrix_sync(bf, &Vs[s][kf * 16][cw * 32 + nf * 16], 72);
                wmma::mma_sync(oacc[nf], af, bf, oacc[nf]);
            }
        }
    }
    __syncthreads();
    #pragma unroll
    for (int nf = 0; nf < 2; nf++) {
        wmma::store_matrix_sync(&Ss[rw * 16][cw * 32 + nf * 16], oacc[nf], 68,
                                wmma::mem_row_major);
    }
    __syncthreads();
    {
        int row = tid >> 2;
        int cseg = (tid & 3) * 16;
        float inv = 1.0f / lsum[row];
        size_t base = (size_t)(b * N_ + n0 + row) * D_ + h * HD_ + cseg;
        __half2 hv[8];
        #pragma unroll
        for (int j = 0; j < 8; j++) {
            hv[j] = __floats2half2_rn(Ss[row][cseg + 2 * j] * inv,
                                      Ss[row][cseg + 2 * j + 1] * inv);
        }
        *reinterpret_cast<uint4*>(&g_oh[base])     = *reinterpret_cast<uint4*>(&hv[0]);
        *reinterpret_cast<uint4*>(&g_oh[base + 8]) = *reinterpret_cast<uint4*>(&hv[4]);
    }
}

// -------------------- host launch --------------------
extern "C" void kernel_launch(void* const* d_in, const int* in_sizes, int n_in,
                              void* d_out, int out_size) {
    const float* x      = (const float*)d_in[0];
    const float* ctx    = (const float*)d_in[1];
    const float* q_w    = (const float*)d_in[2];
    const float* q_b    = (const float*)d_in[3];
    const float* kv_w   = (const float*)d_in[4];
    const float* kv_b   = (const float*)d_in[5];
    const float* proj_w = (const float*)d_in[6];
    const float* proj_b = (const float*)d_in[7];
    float* out = (float*)d_out;

    __half* p_xh = 0;
    __half* p_qwh = 0;
    __half* p_kvwh = 0;
    __half* p_pwh = 0;
    cudaGetSymbolAddress((void**)&p_xh,   g_xh);
    cudaGetSymbolAddress((void**)&p_qwh,  g_qwh);
    cudaGetSymbolAddress((void**)&p_kvwh, g_kvwh);
    cudaGetSymbolAddress((void**)&p_pwh,  g_pwh);

    {
        int n4 = (MROWS * D_) / 4;
        f2h_kernel<<<(n4 + 255) / 256, 256>>>((const float4*)x, (__half2*)p_xh, n4);
    }
    {
        int n4 = (D_ * D_) / 4;
        f2h_kernel<<<(n4 + 255) / 256, 256>>>((const float4*)q_w, (__half2*)p_qwh, n4);
        f2h_kernel<<<(n4 + 255) / 256, 256>>>((const float4*)proj_w, (__half2*)p_pwh, n4);
    }
    {
        int n4 = (D_ * 2 * D_) / 4;
        f2h_kernel<<<(n4 + 255) / 256, 256>>>((const float4*)kv_w, (__half2*)p_kvwh, n4);
    }
    rmsnorm_kernel<<<MROWS, 256>>>(ctx);

    gemm_q_kernel <<<dim3(1024 / 128, MROWS / 128), 256>>>(q_b);
    gemm_kv_kernel<<<dim3(2048 / 128, MROWS / 128), 256>>>(kv_b);

    flash_kernel<<<dim3(N_ / 64, H_, B_), 256>>>();

    gemm_proj_kernel<<<dim3(1024 / 128, MROWS / 128), 256>>>(proj_b, out);

    // attn.mean() == 1/K exactly (softmax rows sum to 1)
    if (out_size > OUT_ELEMS) {
        int tail = out_size - OUT_ELEMS;
        tail_fill_kernel<<<(tail + 255) / 256, 256>>>(out, OUT_ELEMS, out_size,
                                                      1.0f / (float)KC_);
    }
}